// round 9
// baseline (speedup 1.0000x reference)
#include <cuda_runtime.h>
#include <cstdint>
#include <cstddef>

#define NN 100000
#define NE 600000
#define D  128
#define NR 16
#define NB 8

// ---------------- scratch (device globals only; no allocations) ----------------
__device__ float g_W[(NR + 1) * D * D];   // 16 relation matrices + transposed w_self
__device__ int   g_bucket[NE];
__device__ int   g_cnt[NR];
__device__ int   g_off[NR];
__device__ int   g_pos[NR];
__device__ int   g_is64;                  // 1 if indices are int64, 0 if int32

// ---------------- small helpers ----------------
__device__ __forceinline__ unsigned long long fma2(unsigned long long a,
                                                   unsigned long long b,
                                                   unsigned long long c) {
    unsigned long long d;
    asm("fma.rn.f32x2 %0, %1, %2, %3;" : "=l"(d) : "l"(a), "l"(b), "l"(c));
    return d;
}
__device__ __forceinline__ unsigned long long pack2(float v) {
    unsigned long long d;
    unsigned int u = __float_as_uint(v);
    asm("mov.b64 %0, {%1, %2};" : "=l"(d) : "r"(u), "r"(u));
    return d;
}
// dtype-agnostic index load (logical element i)
__device__ __forceinline__ long long ld_idx(const void* p, int i) {
    return g_is64 ? ((const long long*)p)[i] : (long long)((const int*)p)[i];
}

// ---------------- K_detect: int32 vs int64 index dtype ----------------
__global__ void k_detect(const void* etype_raw) {
    if (threadIdx.x == 0 && blockIdx.x == 0) {
        // If int64 with values in [0,16): every odd int32 word (high half) == 0.
        // If int32: odd words are random 0..15 -> some nonzero in 2000 samples.
        const int* p = (const int*)etype_raw;
        int is64 = 1;
        for (int i = 1; i < 2000; i += 2) {
            if (p[i] != 0) { is64 = 0; break; }
        }
        g_is64 = is64;
    }
}

// ---------------- K0: build relation weights + transposed self weight ----------------
__global__ void k_weights(const float* __restrict__ bases,
                          const float* __restrict__ coeff,
                          const float* __restrict__ wself) {
    int idx = blockIdx.x * blockDim.x + threadIdx.x;
    const int total = (NR + 1) * D * D;
    if (idx >= total) return;
    int r  = idx / (D * D);
    int ko = idx - r * (D * D);
    if (r < NR) {
        float s = 0.f;
#pragma unroll
        for (int b = 0; b < NB; b++)
            s += coeff[r * NB + b] * bases[b * D * D + ko];
        g_W[idx] = s;
    } else {
        int k = ko >> 7, o = ko & 127;
        g_W[idx] = wself[o * D + k];   // W16[k][o] = w_self[o][k]
    }
}

// ---------------- K1: bucket edges by relation ----------------
__global__ void k_zero() {
    int t = threadIdx.x;
    if (t < NR) g_cnt[t] = 0;
}

__global__ void k_hist(const void* __restrict__ etype) {
    __shared__ int h[NR];
    if (threadIdx.x < NR) h[threadIdx.x] = 0;
    __syncthreads();
    for (int e = blockIdx.x * blockDim.x + threadIdx.x; e < NE;
         e += gridDim.x * blockDim.x) {
        unsigned rel = (unsigned)ld_idx(etype, e);
        if (rel < NR) atomicAdd(&h[rel], 1);   // guard: fault-proof
    }
    __syncthreads();
    if (threadIdx.x < NR) atomicAdd(&g_cnt[threadIdx.x], h[threadIdx.x]);
}

__global__ void k_scan() {
    if (threadIdx.x == 0) {
        int acc = 0;
        for (int r = 0; r < NR; r++) {
            g_off[r] = acc;
            g_pos[r] = acc;
            acc += g_cnt[r];
        }
    }
}

__global__ void k_scatter(const void* __restrict__ etype) {
    __shared__ int h[NR];
    __shared__ int base[NR];
    if (threadIdx.x < NR) { h[threadIdx.x] = 0; base[threadIdx.x] = 0; }
    __syncthreads();
    int e = blockIdx.x * blockDim.x + threadIdx.x;
    int rel = 0, rank = 0;
    bool ok = false;
    if (e < NE) {
        unsigned rr = (unsigned)ld_idx(etype, e);
        if (rr < NR) {
            rel = (int)rr;
            ok  = true;
            rank = atomicAdd(&h[rel], 1);
        }
    }
    __syncthreads();
    if (threadIdx.x < NR && h[threadIdx.x] > 0)
        base[threadIdx.x] = atomicAdd(&g_pos[threadIdx.x], h[threadIdx.x]);
    __syncthreads();
    if (ok) g_bucket[base[rel] + rank] = e;
}

// ---------------- K2/K3: apply (self-loop stores / edge messages atomics) ----------------
// 512 threads, 16 warps. SMEM: 64KB weights + 16 warps * 8 edges * 128 * 8B staged
// pre-duplicated f32x2 source values = 128KB staging -> 192KB total, 1 CTA/SM.
// One warp processes 8 sources per iteration: each LDS.128 of weights is reused
// for 8 edges (SMEM BW 64B/cyc/SM < 128 crossbar), inner product via fma.rn.f32x2.
#define SMEM_BYTES (65536 + 16 * 8 * 128 * 8)

template <bool SELF>
__global__ void __launch_bounds__(512, 1)
k_apply(const float* __restrict__ x,
        const void* __restrict__ eidx,
        float* __restrict__ out) {
    extern __shared__ unsigned long long smbuf[];
    unsigned long long* Wull  = smbuf;          // 8192 ull = 64KB
    unsigned long long* stage = smbuf + 8192;

    const int r   = SELF ? NR : blockIdx.y;
    const int tid = threadIdx.x;

    // stage this relation's 128x128 weight matrix in SMEM
    {
        const float4* src = (const float4*)(g_W + r * (D * D));
        float4* dst = (float4*)Wull;
#pragma unroll
        for (int i = 0; i < 8; i++)          // 8 * 512 = 4096 float4 = 16384 floats
            dst[tid + i * 512] = src[tid + i * 512];
    }
    __syncthreads();

    const int nr   = SELF ? NN : g_cnt[r];
    const int base = SELF ? 0 : g_off[r];
    const int warp = tid >> 5, lane = tid & 31;
    unsigned long long* st = stage + warp * 1024;   // 8 edges * 128 k
    const ulonglong2* W2 = (const ulonglong2*)Wull;
    const int ngroups = (nr + 7) >> 3;
    const int warps_total = gridDim.x * 16;

    for (int gi = blockIdx.x * 16 + warp; gi < ngroups; gi += warps_total) {
        // lanes 0..7 fetch metadata for one source each
        int myRow = 0, myCol = 0, myOk = 0;
        if (lane < 8) {
            int ei = gi * 8 + lane;
            if (ei < nr) {
                myOk = 1;
                if (SELF) {
                    myRow = ei; myCol = ei;
                } else {
                    int e = g_bucket[base + ei];
                    // clamp: never fault even if indices are unexpectedly bad
                    long long rw = ld_idx(eidx, e);
                    long long cl = ld_idx(eidx, NE + e);
                    myRow = (int)(rw < 0 ? 0 : (rw >= NN ? NN - 1 : rw));
                    myCol = (int)(cl < 0 ? 0 : (cl >= NN ? NN - 1 : cl));
                }
            }
        }
        __syncwarp();

        // stage 8 source rows as duplicated f32x2 pairs
#pragma unroll
        for (int g = 0; g < 8; g++) {
            int col = __shfl_sync(0xffffffffu, myCol, g);
            float4 v = ((const float4*)(x + (size_t)col * D))[lane];
            st[g * 128 + lane * 4 + 0] = pack2(v.x);
            st[g * 128 + lane * 4 + 1] = pack2(v.y);
            st[g * 128 + lane * 4 + 2] = pack2(v.z);
            st[g * 128 + lane * 4 + 3] = pack2(v.w);
        }
        __syncwarp();

        unsigned long long acc[8][2];
#pragma unroll
        for (int g = 0; g < 8; g++) { acc[g][0] = 0ull; acc[g][1] = 0ull; }

#pragma unroll 4
        for (int k = 0; k < D; k++) {
            ulonglong2 w = W2[k * 32 + lane];   // W[k][lane*4 .. lane*4+3]
#pragma unroll
            for (int g = 0; g < 8; g++) {
                unsigned long long xk2 = st[g * 128 + k];  // broadcast LDS
                acc[g][0] = fma2(xk2, w.x, acc[g][0]);
                acc[g][1] = fma2(xk2, w.y, acc[g][1]);
            }
        }

#pragma unroll
        for (int g = 0; g < 8; g++) {
            int ok  = __shfl_sync(0xffffffffu, myOk, g);
            int row = __shfl_sync(0xffffffffu, myRow, g);
            if (ok) {
                float v0 = __uint_as_float((unsigned int)acc[g][0]);
                float v1 = __uint_as_float((unsigned int)(acc[g][0] >> 32));
                float v2 = __uint_as_float((unsigned int)acc[g][1]);
                float v3 = __uint_as_float((unsigned int)(acc[g][1] >> 32));
                float* p = out + (size_t)row * D + lane * 4;
                if (SELF) {
                    float4 res; res.x = v0; res.y = v1; res.z = v2; res.w = v3;
                    *(float4*)p = res;
                } else {
                    asm volatile(
                        "red.global.add.v4.f32 [%0], {%1, %2, %3, %4};"
                        :: "l"(p), "f"(v0), "f"(v1), "f"(v2), "f"(v3)
                        : "memory");
                }
            }
        }
        __syncwarp();
    }
}

// ---------------- launcher ----------------
extern "C" void kernel_launch(void* const* d_in, const int* in_sizes, int n_in,
                              void* d_out, int out_size) {
    // Map inputs by element count (order-proof): all six counts are distinct.
    // Element counts are dtype-invariant (int32 vs int64), so this holds either way.
    const float* x     = nullptr;
    const void*  eidx  = nullptr;
    const void*  etype = nullptr;
    const float* bases = nullptr;
    const float* coeff = nullptr;
    const float* wself = nullptr;
    for (int i = 0; i < n_in; i++) {
        switch (in_sizes[i]) {
            case NN * D:      x     = (const float*)d_in[i]; break; // 12,800,000
            case 2 * NE:      eidx  = d_in[i];               break; //  1,200,000
            case NE:          etype = d_in[i];               break; //    600,000
            case NB * D * D:  bases = (const float*)d_in[i]; break; //    131,072
            case NR * NB:     coeff = (const float*)d_in[i]; break; //        128
            case D * D:       wself = (const float*)d_in[i]; break; //     16,384
            default: break;
        }
    }
    float* out = (float*)d_out;

    cudaFuncSetAttribute((const void*)k_apply<true>,
                         cudaFuncAttributeMaxDynamicSharedMemorySize, SMEM_BYTES);
    cudaFuncSetAttribute((const void*)k_apply<false>,
                         cudaFuncAttributeMaxDynamicSharedMemorySize, SMEM_BYTES);

    // prep
    k_detect<<<1, 32>>>(etype);
    k_weights<<<((NR + 1) * D * D + 255) / 256, 256>>>(bases, coeff, wself);
    k_zero<<<1, 32>>>();
    k_hist<<<256, 256>>>(etype);
    k_scan<<<1, 32>>>();
    k_scatter<<<(NE + 255) / 256, 256>>>(etype);

    // self-loop initializes every row of out (stores, no atomics)
    k_apply<true><<<148, 512, SMEM_BYTES>>>(x, eidx, out);
    // per-relation edge messages, scatter-added with vectorized reductions
    k_apply<false><<<dim3(9, 16), 512, SMEM_BYTES>>>(x, eidx, out);
}